// round 13
// baseline (speedup 1.0000x reference)
#include <cuda_runtime.h>
#include <cuda_fp16.h>
#include <math.h>
#include <stdint.h>

#define BATCH 2
#define NHEAD 8
#define DM 512
#define HD 512
#define TT 8
#define HH 28
#define WWW 28
#define LL 6273          // 1 + 8*28*28
#define LP 1569          // 1 + 8*14*14
#define LPP 1600         // padded K for attention GEMMs
#define NP 1568
#define BHN 16           // BATCH*NHEAD
#define ATT_SCALE 0.04419417382415922f   // 1/sqrt(512)

// ---------------- scratch (static device allocations) ----------------
__device__ __align__(256) __half g_xr  [BATCH * LL * DM];       // half x
__device__ __align__(256) __half g_Wdr [DM * NHEAD * HD];       // half Wd
__device__ __align__(256) __half g_wp  [4][HD * 2048];          // packed half pool weights [n][p*512+ci]
__device__ __align__(256) __half g_WqT [3][DM * NHEAD * HD];    // half W^T: [d][h*512+ci]
__device__ __align__(256) __half g_Weff[3 * NHEAD * HD * 2048]; // [s][h][co][p*512+d]
__device__ __align__(256) float  g_be  [3][NHEAD * HD];         // pooled bias (fp32)
__device__ __align__(256) float  g_PQ  [BHN * LP * HD];         // raw fp32 (residual / row0)
__device__ __align__(256) __half g_PQr [BHN * LP * HD];         // half (logits a)
__device__ __align__(256) float  g_PK  [BHN * LP * HD];         // raw fp32 (row0)
__device__ __align__(256) __half g_PVt [BHN * HD * LPP];        // half, k-padded (pad stays 0)
__device__ __align__(256) __half g_Kmod[BHN * LP * HD];         // half scale*PK+emb
__device__ __align__(256) float  g_logits[BHN * LP * LPP];      // fp32, stride LPP
__device__ __align__(256) __half g_probs[BHN * LP * LPP];       // half probs, pad zero
__device__ __align__(256) __half g_att [BHN * LP * HD];         // half (+residual)
__device__ __align__(256) float  g_PX  [BATCH * LP * HD];       // fp32
__device__ __align__(256) float  g_emb [NP * HD];
__device__ __align__(256) float  g_y   [BATCH * LP * HD];

__device__ __forceinline__ __half h16(float v) { return __float2half_rn(v); }

__device__ __forceinline__ void cp16(uint32_t dst, const __half* src, bool valid) {
    if (valid)
        asm volatile("cp.async.cg.shared.global [%0], [%1], 16;\n" :: "r"(dst), "l"(src));
    else
        asm volatile("cp.async.cg.shared.global [%0], [%1], 16, %2;\n" :: "r"(dst), "l"(src), "r"(0));
}

__device__ __forceinline__ void ldsm4(unsigned& r0, unsigned& r1, unsigned& r2, unsigned& r3,
                                      uint32_t addr) {
    asm volatile("ldmatrix.sync.aligned.m8n8.x4.shared.b16 {%0,%1,%2,%3}, [%4];"
                 : "=r"(r0), "=r"(r1), "=r"(r2), "=r"(r3) : "r"(addr));
}

// ---------------- fp16 GEMM: 128x128x32 tiles, 128 threads, 64x64 warp tile,
// ---------------- ldmatrix.x4 fragments, 3-stage cp.async pipeline -----------
#define KT 32
#define RSH 40                                   // halves per smem row (32 data + 8 pad)
#define STAGE_H (2 * 128 * RSH)                  // halves per stage (A+B)
#define SMEM_DYN (3 * STAGE_H * 2)               // 61440 bytes

template <class OP>
__global__ void __launch_bounds__(128, 2) gemm_tc(OP op) {
    extern __shared__ __half smh[];
    __shared__ int aT[128], bT[128];

    const int z  = blockIdx.z;
    const int bm = blockIdx.y * 128;
    const int bn = blockIdx.x * 128;
    const int tid = threadIdx.x, lane = tid & 31;
    const int wid = tid >> 5;
    const int wm = (wid & 1) * 64, wn = (wid >> 1) * 64;
    const int r = lane >> 2, c = lane & 3;

    {
        int gm = bm + tid; aT[tid] = (gm < op.M) ? op.arow(z, gm) : -1;
        int gn = bn + tid; bT[tid] = (gn < op.N) ? op.brow(z, gn) : -1;
    }
    __syncthreads();

    const __half* aB = op.abase(z);
    const __half* bB = op.bbase(z);

    const int aoff = aT[tid], boff = bT[tid];

    // ldmatrix per-lane source row/col within the warp tile
    const int mat = lane >> 3, lr = lane & 7;
    const int a_row = (mat & 1) * 8 + lr, a_col = (mat >> 1) * 8;
    const int b_row = (mat >> 1) * 8 + lr, b_col = (mat & 1) * 8;

    const uint32_t smu = (uint32_t)__cvta_generic_to_shared(smh);

    float acc[4][8][4];
#pragma unroll
    for (int i = 0; i < 4; i++)
#pragma unroll
        for (int j = 0; j < 8; j++)
#pragma unroll
            for (int e = 0; e < 4; e++) acc[i][j][e] = 0.f;

    auto FETCH = [&](int kb, int st) {
        uint32_t as = smu + (uint32_t)(st * STAGE_H) * 2u;
        uint32_t bs = as + (uint32_t)(128 * RSH) * 2u;
#pragma unroll
        for (int ch = 0; ch < 4; ch++) {
            int gk = kb * KT + ch * 8;
            int ak = op.akoff(gk), bk = op.bkoff(gk);
            uint32_t off = (uint32_t)(tid * RSH + ch * 8) * 2u;
            cp16(as + off, aB + (aoff < 0 ? 0 : aoff + ak), aoff >= 0);
            cp16(bs + off, bB + (boff < 0 ? 0 : boff + bk), boff >= 0);
        }
        asm volatile("cp.async.commit_group;\n" ::: "memory");
    };

    auto COMPUTE = [&](int st) {
        uint32_t A = smu + (uint32_t)(st * STAGE_H) * 2u;
        uint32_t B = A + (uint32_t)(128 * RSH) * 2u;
#pragma unroll
        for (int ks = 0; ks < KT; ks += 16) {
            unsigned af[4][4], bf[8][2];
#pragma unroll
            for (int mt = 0; mt < 4; mt++) {
                uint32_t addr = A + (uint32_t)(((wm + mt * 16 + a_row) * RSH + ks + a_col) * 2);
                ldsm4(af[mt][0], af[mt][1], af[mt][2], af[mt][3], addr);
            }
#pragma unroll
            for (int np = 0; np < 4; np++) {
                uint32_t addr = B + (uint32_t)(((wn + np * 16 + b_row) * RSH + ks + b_col) * 2);
                ldsm4(bf[2 * np][0], bf[2 * np][1], bf[2 * np + 1][0], bf[2 * np + 1][1], addr);
            }
#pragma unroll
            for (int mt = 0; mt < 4; mt++)
#pragma unroll
                for (int nt = 0; nt < 8; nt++) {
                    asm volatile(
                        "mma.sync.aligned.m16n8k16.row.col.f32.f16.f16.f32 "
                        "{%0,%1,%2,%3}, {%4,%5,%6,%7}, {%8,%9}, {%0,%1,%2,%3};\n"
                        : "+f"(acc[mt][nt][0]), "+f"(acc[mt][nt][1]),
                          "+f"(acc[mt][nt][2]), "+f"(acc[mt][nt][3])
                        : "r"(af[mt][0]), "r"(af[mt][1]), "r"(af[mt][2]), "r"(af[mt][3]),
                          "r"(bf[nt][0]), "r"(bf[nt][1]));
                }
        }
    };

    const int nkb = op.K / KT;
    FETCH(0, 0);
    if (nkb > 1) FETCH(1, 1);
    for (int kb = 0; kb < nkb; kb++) {
        if (kb + 1 < nkb)
            asm volatile("cp.async.wait_group 1;\n" ::: "memory");
        else
            asm volatile("cp.async.wait_group 0;\n" ::: "memory");
        __syncthreads();
        if (kb + 2 < nkb) FETCH(kb + 2, (kb + 2) % 3);
        COMPUTE(kb % 3);
    }

#pragma unroll
    for (int mt = 0; mt < 4; mt++) {
        int m0 = bm + wm + mt * 16 + r;
#pragma unroll
        for (int nt = 0; nt < 8; nt++) {
            int n0 = bn + wn + nt * 8 + 2 * c;
            if (m0 < op.M) {
                if (n0     < op.N) op.store(z, m0, n0,     acc[mt][nt][0]);
                if (n0 + 1 < op.N) op.store(z, m0, n0 + 1, acc[mt][nt][1]);
            }
            if (m0 + 8 < op.M) {
                if (n0     < op.N) op.store(z, m0 + 8, n0,     acc[mt][nt][2]);
                if (n0 + 1 < op.N) op.store(z, m0 + 8, n0 + 1, acc[mt][nt][3]);
            }
        }
    }
}

// ---------------- functors ----------------
// Weff[s,h,p][co,d] = sum_ci wp_s[co,ci,p] * W_s[h*512+ci, d];  z = s*32 + h*4 + p
struct OpWeff {
    int M, N, K;
    __device__ __forceinline__ const __half* abase(int z) const {
        return g_wp[z >> 5];
    }
    __device__ __forceinline__ const __half* bbase(int z) const {
        return &g_WqT[z >> 5][0];
    }
    __device__ __forceinline__ int arow(int z, int m) const {
        return m * 2048 + (z & 3) * 512;
    }
    __device__ __forceinline__ int akoff(int k) const { return k; }
    __device__ __forceinline__ int brow(int z, int n) const {
        return n * (NHEAD * HD) + ((z >> 2) & 7) * 512;
    }
    __device__ __forceinline__ int bkoff(int k) const { return k; }
    __device__ __forceinline__ void store(int z, int m, int n, float v) const {
        int s = z >> 5, h = (z >> 2) & 7, p = z & 3;
        g_Weff[(((s * NHEAD + h) * HD) + m) * 2048 + p * 512 + n] = h16(v);
    }
};

// pooled projection: z=(b,h); a = im2col(x), b = Weff[s,h]; K=2048
struct OpPoolP {
    int sel;             // 0=Q,1=K,2=V
    int M, N, K;
    __device__ __forceinline__ const __half* abase(int) const { return g_xr; }
    __device__ __forceinline__ const __half* bbase(int z) const {
        return g_Weff + (sel * NHEAD + (z & 7)) * (HD * 2048);
    }
    __device__ __forceinline__ int arow(int z, int m) const {
        int t = m / 196, rem = m % 196;
        int hy = rem / 14, wx = rem % 14;
        int l00 = 1 + (t * HH + 2 * hy) * WWW + 2 * wx;
        return ((z >> 3) * LL + l00) * DM;
    }
    __device__ __forceinline__ int akoff(int k) const {
        int p = k >> 9;
        return (k & 511) + ((p >> 1) * WWW + (p & 1)) * DM;
    }
    __device__ __forceinline__ int brow(int, int n) const { return n * 2048; }
    __device__ __forceinline__ int bkoff(int k) const { return k; }
    __device__ __forceinline__ void store(int z, int m, int n, float v) const {
        v += g_be[sel][(z & 7) * 512 + n];
        if (sel == 0) {
            int idx = (z * LP + 1 + m) * HD + n;
            g_PQ[idx] = v;
            g_PQr[idx] = h16(v);
        } else if (sel == 1) {
            int idx = (z * LP + 1 + m) * HD + n;
            g_PK[idx] = v;
            g_Kmod[idx] = h16(ATT_SCALE * v + g_emb[m * HD + n]);
        } else {
            g_PVt[(z * HD + n) * LPP + 1 + m] = h16(v);
        }
    }
};

// x pooling: z = b
struct OpPoolX {
    int M, N, K;
    __device__ __forceinline__ const __half* abase(int) const { return g_xr; }
    __device__ __forceinline__ const __half* bbase(int) const { return g_wp[3]; }
    __device__ __forceinline__ int arow(int z, int m) const {
        int t = m / 196, rem = m % 196;
        int hy = rem / 14, wx = rem % 14;
        int l00 = 1 + (t * HH + 2 * hy) * WWW + 2 * wx;
        return (z * LL + l00) * DM;
    }
    __device__ __forceinline__ int akoff(int k) const {
        int p = k >> 9;
        return (k & 511) + ((p >> 1) * WWW + (p & 1)) * DM;
    }
    __device__ __forceinline__ int brow(int, int n) const { return n * 2048; }
    __device__ __forceinline__ int bkoff(int k) const { return k; }
    __device__ __forceinline__ void store(int z, int m, int n, float v) const {
        g_PX[(z * LP + 1 + m) * HD + n] = v;
    }
};

struct OpLogits {
    int M, N, K;
    __device__ __forceinline__ const __half* abase(int) const { return g_PQr; }
    __device__ __forceinline__ const __half* bbase(int) const { return g_Kmod; }
    __device__ __forceinline__ int arow(int z, int m) const { return (z * LP + m) * HD; }
    __device__ __forceinline__ int akoff(int k) const { return k; }
    __device__ __forceinline__ int brow(int z, int n) const { return (z * LP + n) * HD; }
    __device__ __forceinline__ int bkoff(int k) const { return k; }
    __device__ __forceinline__ void store(int z, int m, int n, float v) const {
        g_logits[(z * LP + m) * LPP + n] = v;
    }
};

struct OpAV {
    int M, N, K;
    __device__ __forceinline__ const __half* abase(int) const { return g_probs; }
    __device__ __forceinline__ const __half* bbase(int) const { return g_PVt; }
    __device__ __forceinline__ int arow(int z, int m) const { return (z * LP + m) * LPP; }
    __device__ __forceinline__ int akoff(int k) const { return k; }
    __device__ __forceinline__ int brow(int z, int n) const { return (z * HD + n) * LPP; }
    __device__ __forceinline__ int bkoff(int k) const { return k; }
    __device__ __forceinline__ void store(int z, int m, int n, float v) const {
        float pq = g_PQ[(z * LP + m) * HD + n];
        g_att[(z * LP + m) * HD + n] = h16(v + (m == 0 ? 1.f : 2.f) * pq);
    }
};

struct OpY {
    const float* bd;
    int M, N, K;
    __device__ __forceinline__ const __half* abase(int) const { return g_att; }
    __device__ __forceinline__ const __half* bbase(int) const { return g_Wdr; }
    __device__ __forceinline__ int arow(int, int m) const {
        int bb = m / LP, q = m % LP;
        return (bb * NHEAD * LP + q) * HD;
    }
    __device__ __forceinline__ int akoff(int k) const {
        return (k >> 9) * (LP * HD) + (k & 511);
    }
    __device__ __forceinline__ int brow(int, int n) const { return n * (NHEAD * HD); }
    __device__ __forceinline__ int bkoff(int k) const { return k; }
    __device__ __forceinline__ void store(int, int m, int n, float v) const {
        g_y[m * DM + n] = v + bd[n] + g_PX[m * DM + n];
    }
};

// ---------------- small kernels ----------------
__global__ void round_k(__half* dst, const float* src, int n) {
    int i = blockIdx.x * 256 + threadIdx.x;
    if (i < n) dst[i] = h16(src[i]);
}

__global__ void pack_k(__half* dst, const float* src) {
    int i = blockIdx.x * 256 + threadIdx.x;
    if (i >= HD * 2048) return;
    int ci = i & 511, patch = (i >> 9) & 3, n = i >> 11;
    dst[n * 2048 + patch * 512 + ci] = h16(src[n * 2048 + ci * 4 + patch]);
}

__global__ void transW_k(const float* Wq, const float* Wk, const float* Wv) {
    __shared__ float t[32][33];
    int zz = blockIdx.z;
    const float* src = zz == 0 ? Wq : (zz == 1 ? Wk : Wv);
    __half* dst = &g_WqT[zz][0];
    int bx = blockIdx.x * 32;
    int by = blockIdx.y * 32;
    int tx = threadIdx.x, ty = threadIdx.y;
#pragma unroll
    for (int i = 0; i < 4; i++)
        t[ty + i * 8][tx] = src[(by + ty + i * 8) * DM + bx + tx];
    __syncthreads();
#pragma unroll
    for (int i = 0; i < 4; i++)
        dst[(bx + ty + i * 8) * (NHEAD * HD) + by + tx] = h16(t[tx][ty + i * 8]);
}

__global__ void biaseff_k(const float* wpq, const float* wpk, const float* wpv,
                          const float* bq, const float* bk, const float* bv) {
    int s = blockIdx.y;
    const float* w = s == 0 ? wpq : (s == 1 ? wpk : wpv);
    const float* b = s == 0 ? bq : (s == 1 ? bk : bv);
    int gw = blockIdx.x * 8 + (threadIdx.x >> 5);
    int lane = threadIdx.x & 31;
    int h = gw >> 9, co = gw & 511;
    float sum = 0.f;
    for (int ci = lane; ci < 512; ci += 32) {
        const float* wp4 = w + co * 2048 + ci * 4;
        sum += (wp4[0] + wp4[1] + wp4[2] + wp4[3]) * b[h * 512 + ci];
    }
#pragma unroll
    for (int o = 16; o; o >>= 1) sum += __shfl_xor_sync(0xffffffffu, sum, o);
    if (lane == 0) g_be[s][gw] = sum;
}

__global__ void clsproj_k(const float* x,
                          const float* Wq, const float* Wk, const float* Wv,
                          const float* bq, const float* bk, const float* bv) {
    int s = blockIdx.y;
    const float* W = s == 0 ? Wq : (s == 1 ? Wk : Wv);
    const float* bb = s == 0 ? bq : (s == 1 ? bk : bv);
    int gw = blockIdx.x * 8 + (threadIdx.x >> 5);
    int lane = threadIdx.x & 31;
    int z = gw >> 9, c = gw & 511;
    int b = z >> 3, h = z & 7;
    const float* xr = x + (long long)b * LL * DM;
    const float* wr = W + (h * 512 + c) * DM;
    float sum = 0.f;
    for (int d = lane; d < DM; d += 32) sum += xr[d] * wr[d];
#pragma unroll
    for (int o = 16; o; o >>= 1) sum += __shfl_xor_sync(0xffffffffu, sum, o);
    if (lane == 0) {
        float v = sum + bb[h * 512 + c];
        if (s == 0) {
            g_PQ[z * LP * HD + c] = v;
            g_PQr[z * LP * HD + c] = h16(v);
        } else if (s == 1) {
            g_PK[z * LP * HD + c] = v;
            g_Kmod[z * LP * HD + c] = h16(ATT_SCALE * v);
        } else {
            g_PVt[(z * HD + c) * LPP] = h16(v);
        }
    }
}

__global__ void clsx_k(const float* x) {
    int i = blockIdx.x * 256 + threadIdx.x;
    if (i >= BATCH * DM) return;
    int z = i >> 9, c = i & 511;
    g_PX[z * LP * HD + c] = x[(long long)z * LL * DM + c];
}

__global__ void emb_k() {
    int i = blockIdx.x * 256 + threadIdx.x;
    if (i >= NP * HD) return;
    int tok = i >> 9, d = i & 511;
    int t = tok / 196, rem = tok % 196;
    int hy = rem / 14, wx = rem % 14;
    float pos; int j, half;
    if (d < 170)      { pos = (float)t;  j = d;        half = 85; }
    else if (d < 340) { pos = (float)hy; j = d - 170;  half = 85; }
    else              { pos = (float)wx; j = d - 340;  half = 86; }
    bool is_cos = (j >= half);
    int jj = is_cos ? j - half : j;
    float omega = powf(10000.f, -(float)jj / (float)half);
    float ang = pos * omega;
    g_emb[i] = is_cos ? cosf(ang) : sinf(ang);
}

__global__ void row0_k() {
    int w = (blockIdx.x * blockDim.x + threadIdx.x) >> 5;
    int lane = threadIdx.x & 31;
    if (w >= BHN * LP) return;
    int z = w / LP, n = w % LP;
    const float* q = g_PQ + z * LP * HD;
    const float* kk = g_PK + (z * LP + n) * HD;
    float s = 0.f;
    for (int i = lane; i < HD; i += 32) s += q[i] * kk[i];
#pragma unroll
    for (int o = 16; o; o >>= 1) s += __shfl_xor_sync(0xffffffffu, s, o);
    if (lane == 0) g_logits[(long long)z * LP * LPP + n] = s * ATT_SCALE;
}

__global__ void softmax_k() {
    int row = blockIdx.x;
    float* p = g_logits + (long long)row * LPP;
    __half* pr = g_probs + (long long)row * LPP;
    int tid = threadIdx.x;
    float v[7];
    float m = -1e30f;
#pragma unroll
    for (int i = 0; i < 7; i++) {
        int idx = tid + i * 256;
        v[i] = (idx < LP) ? p[idx] : -1e30f;
        m = fmaxf(m, v[i]);
    }
    __shared__ float red[256];
    red[tid] = m; __syncthreads();
    for (int s = 128; s > 0; s >>= 1) {
        if (tid < s) red[tid] = fmaxf(red[tid], red[tid + s]);
        __syncthreads();
    }
    m = red[0]; __syncthreads();
    float sum = 0.f;
#pragma unroll
    for (int i = 0; i < 7; i++) {
        int idx = tid + i * 256;
        v[i] = (idx < LP) ? expf(v[i] - m) : 0.f;
        sum += v[i];
    }
    red[tid] = sum; __syncthreads();
    for (int s = 128; s > 0; s >>= 1) {
        if (tid < s) red[tid] += red[tid + s];
        __syncthreads();
    }
    float inv = 1.f / red[0];
#pragma unroll
    for (int i = 0; i < 7; i++) {
        int idx = tid + i * 256;
        if (idx < LP) pr[idx] = h16(v[i] * inv);
    }
    if (tid < LPP - LP) pr[LP + tid] = __float2half(0.f);
}

__global__ void ln_k(const float* gamma, const float* beta, float* out) {
    int row = blockIdx.x;
    const float* p = g_y + row * DM;
    int tid = threadIdx.x;
    float v[4];
#pragma unroll
    for (int i = 0; i < 4; i++) v[i] = p[tid + i * 128];
    __shared__ float red[128];
    float s = v[0] + v[1] + v[2] + v[3];
    red[tid] = s; __syncthreads();
    for (int st = 64; st > 0; st >>= 1) {
        if (tid < st) red[tid] += red[tid + st];
        __syncthreads();
    }
    float mu = red[0] / (float)DM;
    __syncthreads();
    float sq = 0.f;
#pragma unroll
    for (int i = 0; i < 4; i++) { float d = v[i] - mu; sq += d * d; }
    red[tid] = sq; __syncthreads();
    for (int st = 64; st > 0; st >>= 1) {
        if (tid < st) red[tid] += red[tid + st];
        __syncthreads();
    }
    float inv = rsqrtf(red[0] / (float)DM + 1e-5f);
    __syncthreads();
#pragma unroll
    for (int i = 0; i < 4; i++) {
        int cc = tid + i * 128;
        out[row * DM + cc] = (v[i] - mu) * inv * gamma[cc] + beta[cc];
    }
}

// ---------------- launch ----------------
extern "C" void kernel_launch(void* const* d_in, const int* in_sizes, int n_in,
                              void* d_out, int out_size) {
    const float* x    = (const float*)d_in[0];
    const float* Wq   = (const float*)d_in[1];
    const float* bq   = (const float*)d_in[2];
    const float* Wk   = (const float*)d_in[3];
    const float* bk   = (const float*)d_in[4];
    const float* Wv   = (const float*)d_in[5];
    const float* bv   = (const float*)d_in[6];
    const float* wpq  = (const float*)d_in[7];
    const float* wpk  = (const float*)d_in[8];
    const float* wpv  = (const float*)d_in[9];
    const float* wpx  = (const float*)d_in[10];
    const float* Wd   = (const float*)d_in[11];
    const float* bd   = (const float*)d_in[12];
    const float* gamma= (const float*)d_in[13];
    const float* beta = (const float*)d_in[14];
    float* out = (float*)d_out;

    __half *p_xr, *p_Wdr, *p_wp;
    cudaGetSymbolAddress((void**)&p_xr,  g_xr);
    cudaGetSymbolAddress((void**)&p_Wdr, g_Wdr);
    cudaGetSymbolAddress((void**)&p_wp,  g_wp);

    cudaFuncSetAttribute(gemm_tc<OpWeff>,   cudaFuncAttributeMaxDynamicSharedMemorySize, SMEM_DYN);
    cudaFuncSetAttribute(gemm_tc<OpPoolP>,  cudaFuncAttributeMaxDynamicSharedMemorySize, SMEM_DYN);
    cudaFuncSetAttribute(gemm_tc<OpPoolX>,  cudaFuncAttributeMaxDynamicSharedMemorySize, SMEM_DYN);
    cudaFuncSetAttribute(gemm_tc<OpLogits>, cudaFuncAttributeMaxDynamicSharedMemorySize, SMEM_DYN);
    cudaFuncSetAttribute(gemm_tc<OpAV>,     cudaFuncAttributeMaxDynamicSharedMemorySize, SMEM_DYN);
    cudaFuncSetAttribute(gemm_tc<OpY>,      cudaFuncAttributeMaxDynamicSharedMemorySize, SMEM_DYN);

    // 0) prep
    int nx = BATCH * LL * DM;
    round_k<<<(nx + 255) / 256, 256>>>(p_xr, x, nx);
    int nw = NHEAD * HD * DM;
    round_k<<<(nw + 255) / 256, 256>>>(p_Wdr, Wd, nw);
    int npk = HD * 2048;
    pack_k<<<(npk + 255) / 256, 256>>>(p_wp + 0 * npk, wpq);
    pack_k<<<(npk + 255) / 256, 256>>>(p_wp + 1 * npk, wpk);
    pack_k<<<(npk + 255) / 256, 256>>>(p_wp + 2 * npk, wpv);
    pack_k<<<(npk + 255) / 256, 256>>>(p_wp + 3 * npk, wpx);
    transW_k<<<dim3(16, 128, 3), dim3(32, 8)>>>(Wq, Wk, Wv);
    emb_k<<<(NP * HD + 255) / 256, 256>>>();
    biaseff_k<<<dim3(512, 3), 256>>>(wpq, wpk, wpv, bq, bk, bv);

    // 1) Weff = wpool @ W
    {
        OpWeff op; op.M = 512; op.N = 512; op.K = 512;
        gemm_tc<<<dim3(4, 4, 96), 128, SMEM_DYN>>>(op);
    }

    // 2) fused pooled projections + x-pool + cls
    {
        OpPoolP op; op.M = NP; op.N = HD; op.K = 2048;
        dim3 g(4, (NP + 127) / 128, BHN);
        op.sel = 0; gemm_tc<<<g, 128, SMEM_DYN>>>(op);
        op.sel = 1; gemm_tc<<<g, 128, SMEM_DYN>>>(op);
        op.sel = 2; gemm_tc<<<g, 128, SMEM_DYN>>>(op);
    }
    {
        OpPoolX op; op.M = NP; op.N = HD; op.K = 2048;
        gemm_tc<<<dim3(4, (NP + 127) / 128, BATCH), 128, SMEM_DYN>>>(op);
    }
    clsproj_k<<<dim3(1024, 3), 256>>>(x, Wq, Wk, Wv, bq, bk, bv);
    clsx_k<<<(BATCH * DM + 255) / 256, 256>>>(x);

    // 3) logits GEMM, row-0 repair, softmax
    {
        OpLogits op; op.M = LP; op.N = LP; op.K = HD;
        gemm_tc<<<dim3((LP + 127) / 128, (LP + 127) / 128, BHN), 128, SMEM_DYN>>>(op);
    }
    row0_k<<<(BHN * LP * 32 + 255) / 256, 256>>>();
    softmax_k<<<BHN * LP, 256>>>();

    // 4) attn @ PV (+residual)
    {
        OpAV op; op.M = LP; op.N = HD; op.K = LPP;
        gemm_tc<<<dim3((HD + 127) / 128, (LP + 127) / 128, BHN), 128, SMEM_DYN>>>(op);
    }

    // 5) output projection + bias + PX, then LayerNorm
    {
        OpY op; op.bd = bd; op.M = BATCH * LP; op.N = DM; op.K = NHEAD * HD;
        gemm_tc<<<dim3((DM + 127) / 128, (op.M + 127) / 128, 1), 128, SMEM_DYN>>>(op);
    }
    ln_k<<<BATCH * LP, 128>>>(gamma, beta, out);
}